// round 16
// baseline (speedup 1.0000x reference)
#include <cuda_runtime.h>
#include <cuda_fp16.h>

#define N_NODES 100000
#define N_EDGES 3200000
#define N_GRAPHS 1000
#define IN_DIM 10
#define HID 20
#define CAP 96
#define BN_EPS 1e-5f

#define NBLK_N ((N_NODES + 255) / 256)      // 391
#define NBLK2  ((N_NODES * 2 + 255) / 256)  // 782 gin blocks (2 threads/node)
#define NB_FILL ((N_EDGES / 4 + 255) / 256) // 3125

// ---- device scratch ----
// Self-restoring invariants (zero-init at load; every call restores them):
//   g_cur: zeroed by k_poolfc (end of pipeline)
//   g_stat[2]: zeroed by k_fillprep; g_stat[0] by gin2; g_stat[1] by gin3
__device__ int   g_cur[N_NODES];
__device__ float g_stat[3][2][HID];                         // atomic BN totals per layer
__device__ __align__(16)  int    g_src[N_NODES * CAP];      // row-major: g_src[i*CAP + k]
__device__ __align__(128) __half g_xh[(N_NODES + 8) * 16];  // x half rows, 10 -> 16 (32B); row N_NODES = zero dummy
__device__ __align__(128) __half g_hh[(N_NODES + 8) * 32];  // h half rows, stride 32 (64B)
__device__ __align__(16)  float  g_tmp[N_NODES * HID];      // pre-BN activations (fp32)

// fused: zero g_stat[2] + convert x to half rows + build reverse adjacency
__global__ void __launch_bounds__(256) k_fillprep(const int* __restrict__ ei,
                                                  const float* __restrict__ x) {
    int gid = blockIdx.x * 256 + threadIdx.x;
    if (gid < 2 * HID) ((float*)g_stat[2])[gid] = 0.f;   // consumed by prev call's poolfc

    if (gid < N_NODES) {
        const float2* xp = (const float2*)(x + (size_t)gid * IN_DIM);
        __half2 h[8];
#pragma unroll
        for (int q = 0; q < 5; q++) { float2 v = xp[q]; h[q] = __floats2half2_rn(v.x, v.y); }
#pragma unroll
        for (int q = 5; q < 8; q++) h[q] = __floats2half2_rn(0.f, 0.f);
        int4* op = (int4*)(g_xh + (size_t)gid * 16);
        op[0] = *(int4*)&h[0];
        op[1] = *(int4*)&h[4];
    }

    if (gid * 4 < N_EDGES) {
        int4 s4 = ((const int4*)ei)[gid];
        int4 d4 = ((const int4*)(ei + N_EDGES))[gid];
        int ss[4] = {s4.x, s4.y, s4.z, s4.w};
        int dd[4] = {d4.x, d4.y, d4.z, d4.w};
#pragma unroll
        for (int q = 0; q < 4; q++) {
            int s = min(max(ss[q], 0), N_NODES - 1);
            int d = min(max(dd[q], 0), N_NODES - 1);
            int p = atomicAdd(&g_cur[d], 1);     // g_cur zero at entry (invariant)
            if (p < CAP) g_src[d * CAP + p] = s;
        }
    }
}

// load NLD int4s of a row as half2s
template <int DP, int NLD>
__device__ __forceinline__ void load_row_h2(__half2* h, const __half* __restrict__ hin, int s) {
    const int4* p = (const int4*)(hin + (size_t)s * DP);
#pragma unroll
    for (int q = 0; q < NLD; q++) {
        int4 v = p[q];
        ((int*)h)[4 * q + 0] = v.x;
        ((int*)h)[4 * q + 1] = v.y;
        ((int*)h)[4 * q + 2] = v.z;
        ((int*)h)[4 * q + 3] = v.w;
    }
}

// fp32 add of one row (node's own row)
template <int DR, int DP, int NLD>
__device__ __forceinline__ void add_row_f(float* acc, const __half* __restrict__ hin, int s) {
    __half2 hb[NLD * 4];
    load_row_h2<DP, NLD>(hb, hin, s);
#pragma unroll
    for (int q = 0; q < DR / 2; q++) {
        float2 f = __half22float2(hb[q]);
        acc[2 * q]     += f.x;
        acc[2 * q + 1] += f.y;
    }
}

// Two threads per node (edge-split halves); 4-edge half2 (HADD2) inner accumulation
// with next-group index prefetch. GEMV fused channel-by-channel with BN stats and
// rolling float4 store (no y[20] array -> lower register pressure, 4 CTAs/SM).
template <int DR, int DP, int NLD, int L, int ZPREV>
__global__ void __launch_bounds__(256, 4) k_gin(const float* __restrict__ W,
                                                const float* __restrict__ bias) {
    __shared__ float sW[DR * HID];
    __shared__ float sb[HID];
    __shared__ float sws[8][HID];
    __shared__ float swq[8][HID];

    const __half* hin = (DR == IN_DIM) ? (const __half*)g_xh : (const __half*)g_hh;

    int t = threadIdx.x;
    if (ZPREV >= 0 && blockIdx.x == 0 && t < 2 * HID)
        ((float*)g_stat[ZPREV])[t] = 0.f;

    for (int j = t; j < DR * HID; j += 256) sW[j] = W[j];
    if (t < HID) sb[t] = bias[t];
    __syncthreads();

    int i = blockIdx.x * 128 + (t >> 1);
    int sub = t & 1;
    bool active = (i < N_NODES);
    int ii = min(i, N_NODES - 1);
    int deg = active ? min(g_cur[ii], CAP) : 0;
    const int* sp = g_src + (size_t)ii * CAP;

    float acc[DR];
#pragma unroll
    for (int d = 0; d < DR; d++) acc[d] = 0.f;

    int m = ((deg >> 1) + 3) & ~3;     // 16B-aligned split point
    if (m > deg) m = deg;
    int kbeg = sub ? m : 0;
    int kend = sub ? deg : m;

    int4 idx;
    if (kbeg < kend) idx = *(const int4*)(sp + kbeg);
    for (int k = kbeg; k < kend; k += 4) {
        int4 cur = idx;
        if (k + 4 < kend) idx = *(const int4*)(sp + k + 4);   // prefetch next group
        int id[4] = {cur.x, cur.y, cur.z, cur.w};
        __half2 hb[NLD * 4];
        __half2 hacc[DR / 2];
        load_row_h2<DP, NLD>(hb, hin, id[0]);
#pragma unroll
        for (int q = 0; q < DR / 2; q++) hacc[q] = hb[q];
#pragma unroll
        for (int j = 1; j < 4; j++) {
            int s = (k + j < kend) ? id[j] : N_NODES;   // dummy zero row
            load_row_h2<DP, NLD>(hb, hin, s);
#pragma unroll
            for (int q = 0; q < DR / 2; q++) hacc[q] = __hadd2(hacc[q], hb[q]);
        }
#pragma unroll
        for (int q = 0; q < DR / 2; q++) {
            float2 f = __half22float2(hacc[q]);
            acc[2 * q]     += f.x;
            acc[2 * q + 1] += f.y;
        }
    }
    if (sub == 0 && active) add_row_f<DR, DP, NLD>(acc, hin, ii);  // own row (eps=0)

    // combine partner's partial into sub0
#pragma unroll
    for (int d = 0; d < DR; d++)
        acc[d] += __shfl_down_sync(0xffffffffu, acc[d], 1);

    // fused GEMV + BN stats + rolling float4 store (channel at a time)
    int lane = t & 31, wwid = t >> 5;
    bool wr = (sub == 0) && active;
    float4 buf;
    float* bufp = (float*)&buf;
#pragma unroll
    for (int j = 0; j < HID; j++) {
        float v = 0.f;
        if (wr) {
            v = sb[j];
#pragma unroll
            for (int d = 0; d < DR; d++) v += acc[d] * sW[d * HID + j];
        }
        bufp[j & 3] = v;
        if ((j & 3) == 3 && wr)
            ((float4*)(g_tmp + (size_t)i * HID))[j >> 2] = buf;
        float s = v, q = v * v;
#pragma unroll
        for (int o = 16; o; o >>= 1) {
            s += __shfl_down_sync(0xffffffff, s, o);
            q += __shfl_down_sync(0xffffffff, q, o);
        }
        if (lane == 0) { sws[wwid][j] = s; swq[wwid][j] = q; }
    }
    __syncthreads();
    if (t < HID) {
        float s = 0.f, q = 0.f;
#pragma unroll
        for (int w = 0; w < 8; w++) { s += sws[w][t]; q += swq[w][t]; }
        atomicAdd(&g_stat[L][0][t], s);
        atomicAdd(&g_stat[L][1][t], q);
    }
}

// pure streaming: finalize BN from g_stat[L] totals, normalize + relu -> g_hh
template <int L>
__global__ void __launch_bounds__(256) k_bnorm(const float* __restrict__ g,
                                               const float* __restrict__ beta) {
    __shared__ float sab[2 * HID];
    int t = threadIdx.x;
    if (t < HID) {
        float s = g_stat[L][0][t], q = g_stat[L][1][t];
        float mu  = s / (float)N_NODES;
        float var = q / (float)N_NODES - mu * mu;
        float a = rsqrtf(var + BN_EPS) * g[t];
        sab[t] = a;
        sab[HID + t] = beta[t] - mu * a;
    }
    __syncthreads();

    int i = blockIdx.x * 256 + t;
    if (i >= N_NODES) return;
    const float4* tp = (const float4*)(g_tmp + (size_t)i * HID);
    __half2 h[12];
#pragma unroll
    for (int q = 0; q < 5; q++) {
        float4 v = tp[q];
        int j = 4 * q;
        float r0 = fmaxf(v.x * sab[j+0] + sab[HID+j+0], 0.f);
        float r1 = fmaxf(v.y * sab[j+1] + sab[HID+j+1], 0.f);
        float r2 = fmaxf(v.z * sab[j+2] + sab[HID+j+2], 0.f);
        float r3 = fmaxf(v.w * sab[j+3] + sab[HID+j+3], 0.f);
        h[2*q]   = __floats2half2_rn(r0, r1);
        h[2*q+1] = __floats2half2_rn(r2, r3);
    }
    h[10] = __floats2half2_rn(0.f, 0.f);
    h[11] = __floats2half2_rn(0.f, 0.f);
    int4* op = (int4*)(g_hh + (size_t)i * 32);
    op[0] = *(int4*)&h[0];
    op[1] = *(int4*)&h[4];
    op[2] = *(int4*)&h[8];
}

// BN-finalize (layer 3 totals) + norm + relu + pool + fc; also restores g_cur = 0.
__global__ void __launch_bounds__(640) k_poolfc(const float* __restrict__ g,
                                                const float* __restrict__ beta,
                                                const int* __restrict__ batch,
                                                const float* __restrict__ fcW,
                                                const float* __restrict__ fcb,
                                                float* __restrict__ out) {
    // restore invariant for next call (nothing here reads g_cur)
    for (int i = blockIdx.x * 640 + threadIdx.x; i < N_NODES; i += 50 * 640)
        g_cur[i] = 0;

    __shared__ float sab[2 * HID];
    int w = threadIdx.x >> 5, lane = threadIdx.x & 31;
    int t = threadIdx.x;
    if (t < HID) {
        float s = g_stat[2][0][t], q = g_stat[2][1][t];
        float mu  = s / (float)N_NODES;
        float var = q / (float)N_NODES - mu * mu;
        float a = rsqrtf(var + BN_EPS) * g[t];
        sab[t] = a;
        sab[HID + t] = beta[t] - mu * a;
    }
    __syncthreads();

    int gid = blockIdx.x * 20 + w;
    if (gid >= N_GRAPHS) return;

    int lo = 0, hi = N_NODES;
    while (lo < hi) { int mid = (lo + hi) >> 1; if (batch[mid] < gid) lo = mid + 1; else hi = mid; }
    int r0 = lo;
    hi = N_NODES;
    while (lo < hi) { int mid = (lo + hi) >> 1; if (batch[mid] < gid + 1) lo = mid + 1; else hi = mid; }
    int r1 = lo;

    float a = 0.f, b = 0.f, w0 = 0.f, w1 = 0.f;
    if (lane < HID) {
        a = sab[lane]; b = sab[HID + lane];
        w0 = fcW[lane * 2 + 0]; w1 = fcW[lane * 2 + 1];
    }
    float p0 = 0.f, p1 = 0.f;
    int n = r0;
    for (; n + 2 <= r1; n += 2) {
        float v0 = (lane < HID) ? g_tmp[(size_t)n * HID + lane] * a + b : 0.f;
        float v1 = (lane < HID) ? g_tmp[(size_t)(n + 1) * HID + lane] * a + b : 0.f;
        p0 += fmaxf(v0, 0.f);
        p1 += fmaxf(v1, 0.f);
    }
    if (n < r1) {
        float v = (lane < HID) ? g_tmp[(size_t)n * HID + lane] * a + b : 0.f;
        p0 += fmaxf(v, 0.f);
    }
    float pool = p0 + p1;
    float o0 = pool * w0, o1 = pool * w1;
#pragma unroll
    for (int o = 16; o; o >>= 1) {
        o0 += __shfl_down_sync(0xffffffff, o0, o);
        o1 += __shfl_down_sync(0xffffffff, o1, o);
    }
    if (lane == 0) {
        out[gid * 2 + 0] = o0 + fcb[0];
        out[gid * 2 + 1] = o1 + fcb[1];
    }
}

extern "C" void kernel_launch(void* const* d_in, const int* in_sizes, int n_in,
                              void* d_out, int out_size) {
    const float* x     = (const float*)d_in[0];
    const int*   ei    = (const int*)d_in[1];
    const int*   batch = (const int*)d_in[2];
    const float* W1  = (const float*)d_in[3];
    const float* b1  = (const float*)d_in[4];
    const float* g1  = (const float*)d_in[5];
    const float* be1 = (const float*)d_in[6];
    const float* W2  = (const float*)d_in[7];
    const float* b2  = (const float*)d_in[8];
    const float* g2  = (const float*)d_in[9];
    const float* be2 = (const float*)d_in[10];
    const float* W3  = (const float*)d_in[11];
    const float* b3  = (const float*)d_in[12];
    const float* g3  = (const float*)d_in[13];
    const float* be3 = (const float*)d_in[14];
    const float* fcW = (const float*)d_in[15];
    const float* fcb = (const float*)d_in[16];
    float* out = (float*)d_out;

    // launch order: 0 fillprep, 1 gin1, 2 bnorm1, 3 gin2, 4 bnorm2,
    // 5 gin3 (<- ncu -s 5 -c 1), 6 poolfc
    k_fillprep<<<NB_FILL, 256>>>(ei, x);

    k_gin<IN_DIM, 16, 2, 0, -1><<<NBLK2, 256>>>(W1, b1);
    k_bnorm<0><<<NBLK_N, 256>>>(g1, be1);

    k_gin<HID, 32, 3, 1, 0><<<NBLK2, 256>>>(W2, b2);
    k_bnorm<1><<<NBLK_N, 256>>>(g2, be2);

    k_gin<HID, 32, 3, 2, 1><<<NBLK2, 256>>>(W3, b3);
    k_poolfc<<<(N_GRAPHS + 19) / 20, 640>>>(g3, be3, batch, fcW, fcb, out);
}

// round 17
// speedup vs baseline: 1.1447x; 1.1447x over previous
#include <cuda_runtime.h>
#include <cuda_fp16.h>

#define N_NODES 100000
#define N_EDGES 3200000
#define N_GRAPHS 1000
#define IN_DIM 10
#define HID 20
#define CAP 96
#define BN_EPS 1e-5f
#define SWS 21

#define NBLK_N ((N_NODES + 255) / 256)      // 391
#define NBLK2  ((N_NODES * 2 + 255) / 256)  // 782 gin blocks (2 threads/node)
#define NB_FILL ((N_EDGES / 4 + 255) / 256) // 3125

// ---- device scratch ----
// Self-restoring invariants (zero-init at load; every call restores them):
//   g_cur: zeroed by k_poolfc; g_stat[2] by k_fillprep; g_stat[0] by gin2; g_stat[1] by gin3
// Pad halfs of g_xh (8-15 beyond ch9) / g_hh (20-31 beyond ch19) and dummy row
// N_NODES are zero: init-zeroed and never written with nonzero.
__device__ int   g_cur[N_NODES];
__device__ float g_stat[3][2][HID];                         // atomic BN totals per layer
__device__ __align__(16)  int    g_src[N_NODES * CAP];      // row-major: g_src[i*CAP + k]
__device__ __align__(128) __half g_xh[(N_NODES + 8) * 16];  // x rows 10 -> stride 16 halfs (32B)
__device__ __align__(128) __half g_hh[(N_NODES + 8) * 32];  // h rows 20 -> stride 32 halfs (64B)
__device__ __align__(16)  float  g_tmp[N_NODES * HID];      // pre-BN activations (fp32)

// fused: zero g_stat[2] + convert x to half rows + build reverse adjacency
__global__ void __launch_bounds__(256) k_fillprep(const int* __restrict__ ei,
                                                  const float* __restrict__ x) {
    int gid = blockIdx.x * 256 + threadIdx.x;
    if (gid < 2 * HID) ((float*)g_stat[2])[gid] = 0.f;

    if (gid < N_NODES) {
        const float2* xp = (const float2*)(x + (size_t)gid * IN_DIM);
        __half2 h[8];
#pragma unroll
        for (int q = 0; q < 5; q++) { float2 v = xp[q]; h[q] = __floats2half2_rn(v.x, v.y); }
#pragma unroll
        for (int q = 5; q < 8; q++) h[q] = __floats2half2_rn(0.f, 0.f);
        int4* op = (int4*)(g_xh + (size_t)gid * 16);
        op[0] = *(int4*)&h[0];
        op[1] = *(int4*)&h[4];
    }

    if (gid * 4 < N_EDGES) {
        int4 s4 = ((const int4*)ei)[gid];
        int4 d4 = ((const int4*)(ei + N_EDGES))[gid];
        int ss[4] = {s4.x, s4.y, s4.z, s4.w};
        int dd[4] = {d4.x, d4.y, d4.z, d4.w};
#pragma unroll
        for (int q = 0; q < 4; q++) {
            int s = min(max(ss[q], 0), N_NODES - 1);
            int d = min(max(dd[q], 0), N_NODES - 1);
            int p = atomicAdd(&g_cur[d], 1);
            if (p < CAP) g_src[d * CAP + p] = s;
        }
    }
}

// load this lane's half of a row (HREGS half2 = DP/4)
template <int DP>
__device__ __forceinline__ void load_half_row(__half2* hb, const __half* __restrict__ hin,
                                              int s, int off) {
    const int4* p = (const int4*)(hin + (size_t)s * DP + off);
    int4 v0 = p[0];
    ((int*)hb)[0] = v0.x; ((int*)hb)[1] = v0.y; ((int*)hb)[2] = v0.z; ((int*)hb)[3] = v0.w;
    if (DP == 32) {
        int4 v1 = p[1];
        ((int*)hb)[4] = v1.x; ((int*)hb)[5] = v1.y; ((int*)hb)[6] = v1.z; ((int*)hb)[7] = v1.w;
    }
}

// Channel-split gather: 2 threads per node (lane pair), lane c owns halfs
// [c*DP/2, (c+1)*DP/2) of each row -> 2 LDG/edge (HID), 1 LDG/edge (layer 1),
// both pair loads in the same 128B line. 4-edge half2 accumulation, index prefetch.
// Distributed GEMV over owned dims, pair-combined by one shfl_xor per channel.
template <int DR, int DP, int L, int ZPREV>
__global__ void __launch_bounds__(256) k_gin(const float* __restrict__ W,
                                             const float* __restrict__ bias) {
    const int HREGS = DP / 4;      // half2 per lane (8 for HID, 4 for layer1)
    const int DL    = DP / 2;      // dims owned per lane (16 / 8)
    __shared__ float sW[32 * SWS]; // zero-padded rows; stride 21 kills pair conflicts
    __shared__ float sb[HID];
    __shared__ float sws[8][HID];
    __shared__ float swq[8][HID];

    const __half* hin = (DR == IN_DIM) ? (const __half*)g_xh : (const __half*)g_hh;

    int t = threadIdx.x;
    if (ZPREV >= 0 && blockIdx.x == 0 && t < 2 * HID)
        ((float*)g_stat[ZPREV])[t] = 0.f;

    for (int j = t; j < 32 * SWS; j += 256) sW[j] = 0.f;
    __syncthreads();
    for (int j = t; j < DR * HID; j += 256) {
        int d = j / HID, cj = j % HID;
        sW[d * SWS + cj] = W[j];
    }
    if (t < HID) sb[t] = bias[t];
    __syncthreads();

    int i = blockIdx.x * 128 + (t >> 1);
    int c = t & 1;
    int off = c * DL;              // half offset of this lane's row chunk
    bool active = (i < N_NODES);
    int ii = min(i, N_NODES - 1);
    int deg = active ? min(g_cur[ii], CAP) : 0;
    const int* sp = g_src + (size_t)ii * CAP;

    float acc[DL];
#pragma unroll
    for (int d = 0; d < DL; d++) acc[d] = 0.f;

    // own row (eps = 0): each lane adds its channel half
    if (active) {
        __half2 hb[HREGS];
        load_half_row<DP>(hb, hin, ii, off);
#pragma unroll
        for (int q = 0; q < HREGS; q++) {
            float2 f = __half22float2(hb[q]);
            acc[2 * q]     += f.x;
            acc[2 * q + 1] += f.y;
        }
    }

    int4 idx;
    if (deg > 0) idx = *(const int4*)(sp);     // pair lanes load same addr (broadcast)
    for (int k = 0; k < deg; k += 4) {
        int4 cur = idx;
        if (k + 4 < deg) idx = *(const int4*)(sp + k + 4);   // prefetch next group
        int id[4] = {cur.x, cur.y, cur.z, cur.w};
        __half2 hb[HREGS];
        __half2 hacc[HREGS];
        load_half_row<DP>(hacc, hin, id[0], off);
#pragma unroll
        for (int j = 1; j < 4; j++) {
            int s = (k + j < deg) ? id[j] : N_NODES;   // dummy zero row
            load_half_row<DP>(hb, hin, s, off);
#pragma unroll
            for (int q = 0; q < HREGS; q++) hacc[q] = __hadd2(hacc[q], hb[q]);
        }
#pragma unroll
        for (int q = 0; q < HREGS; q++) {
            float2 f = __half22float2(hacc[q]);
            acc[2 * q]     += f.x;
            acc[2 * q + 1] += f.y;
        }
    }

    // distributed GEMV over owned dims; pair-combine via shfl_xor(1)
    float y[HID];
#pragma unroll
    for (int j = 0; j < HID; j++) {
        float v = 0.f;
#pragma unroll
        for (int dl = 0; dl < DL; dl++)
            v += acc[dl] * sW[(off + dl) * SWS + j];
        v += __shfl_xor_sync(0xffffffffu, v, 1);
        y[j] = v + sb[j];
    }

    if (active && c == 0) {
        float4* tp = (float4*)(g_tmp + (size_t)i * HID);
#pragma unroll
        for (int j = 0; j < 5; j++)
            tp[j] = make_float4(y[4*j], y[4*j+1], y[4*j+2], y[4*j+3]);
    }
    if (!active || c != 0) {
#pragma unroll
        for (int j = 0; j < HID; j++) y[j] = 0.f;
    }

    // BN stats: warp shfl -> shared -> 40 float atomics per block
    int lane = t & 31, wwid = t >> 5;
#pragma unroll
    for (int j = 0; j < HID; j++) {
        float s = y[j], q = y[j] * y[j];
#pragma unroll
        for (int o = 16; o; o >>= 1) {
            s += __shfl_down_sync(0xffffffff, s, o);
            q += __shfl_down_sync(0xffffffff, q, o);
        }
        if (lane == 0) { sws[wwid][j] = s; swq[wwid][j] = q; }
    }
    __syncthreads();
    if (t < HID) {
        float s = 0.f, q = 0.f;
#pragma unroll
        for (int w = 0; w < 8; w++) { s += sws[w][t]; q += swq[w][t]; }
        atomicAdd(&g_stat[L][0][t], s);
        atomicAdd(&g_stat[L][1][t], q);
    }
}

// pure streaming: finalize BN from g_stat[L] totals, normalize + relu -> g_hh
template <int L>
__global__ void __launch_bounds__(256) k_bnorm(const float* __restrict__ g,
                                               const float* __restrict__ beta) {
    __shared__ float sab[2 * HID];
    int t = threadIdx.x;
    if (t < HID) {
        float s = g_stat[L][0][t], q = g_stat[L][1][t];
        float mu  = s / (float)N_NODES;
        float var = q / (float)N_NODES - mu * mu;
        float a = rsqrtf(var + BN_EPS) * g[t];
        sab[t] = a;
        sab[HID + t] = beta[t] - mu * a;
    }
    __syncthreads();

    int i = blockIdx.x * 256 + t;
    if (i >= N_NODES) return;
    const float4* tp = (const float4*)(g_tmp + (size_t)i * HID);
    __half2 h[12];
#pragma unroll
    for (int q = 0; q < 5; q++) {
        float4 v = tp[q];
        int j = 4 * q;
        float r0 = fmaxf(v.x * sab[j+0] + sab[HID+j+0], 0.f);
        float r1 = fmaxf(v.y * sab[j+1] + sab[HID+j+1], 0.f);
        float r2 = fmaxf(v.z * sab[j+2] + sab[HID+j+2], 0.f);
        float r3 = fmaxf(v.w * sab[j+3] + sab[HID+j+3], 0.f);
        h[2*q]   = __floats2half2_rn(r0, r1);
        h[2*q+1] = __floats2half2_rn(r2, r3);
    }
    h[10] = __floats2half2_rn(0.f, 0.f);
    h[11] = __floats2half2_rn(0.f, 0.f);
    int4* op = (int4*)(g_hh + (size_t)i * 32);
    op[0] = *(int4*)&h[0];
    op[1] = *(int4*)&h[4];
    op[2] = *(int4*)&h[8];
    // halfs 24-31 stay zero (never written)
}

// BN-finalize (layer 3 totals) + norm + relu + pool + fc; also restores g_cur = 0.
__global__ void __launch_bounds__(640) k_poolfc(const float* __restrict__ g,
                                                const float* __restrict__ beta,
                                                const int* __restrict__ batch,
                                                const float* __restrict__ fcW,
                                                const float* __restrict__ fcb,
                                                float* __restrict__ out) {
    for (int i = blockIdx.x * 640 + threadIdx.x; i < N_NODES; i += 50 * 640)
        g_cur[i] = 0;

    __shared__ float sab[2 * HID];
    int w = threadIdx.x >> 5, lane = threadIdx.x & 31;
    int t = threadIdx.x;
    if (t < HID) {
        float s = g_stat[2][0][t], q = g_stat[2][1][t];
        float mu  = s / (float)N_NODES;
        float var = q / (float)N_NODES - mu * mu;
        float a = rsqrtf(var + BN_EPS) * g[t];
        sab[t] = a;
        sab[HID + t] = beta[t] - mu * a;
    }
    __syncthreads();

    int gid = blockIdx.x * 20 + w;
    if (gid >= N_GRAPHS) return;

    int lo = 0, hi = N_NODES;
    while (lo < hi) { int mid = (lo + hi) >> 1; if (batch[mid] < gid) lo = mid + 1; else hi = mid; }
    int r0 = lo;
    hi = N_NODES;
    while (lo < hi) { int mid = (lo + hi) >> 1; if (batch[mid] < gid + 1) lo = mid + 1; else hi = mid; }
    int r1 = lo;

    float a = 0.f, b = 0.f, w0 = 0.f, w1 = 0.f;
    if (lane < HID) {
        a = sab[lane]; b = sab[HID + lane];
        w0 = fcW[lane * 2 + 0]; w1 = fcW[lane * 2 + 1];
    }
    float p0 = 0.f, p1 = 0.f;
    int n = r0;
    for (; n + 2 <= r1; n += 2) {
        float v0 = (lane < HID) ? g_tmp[(size_t)n * HID + lane] * a + b : 0.f;
        float v1 = (lane < HID) ? g_tmp[(size_t)(n + 1) * HID + lane] * a + b : 0.f;
        p0 += fmaxf(v0, 0.f);
        p1 += fmaxf(v1, 0.f);
    }
    if (n < r1) {
        float v = (lane < HID) ? g_tmp[(size_t)n * HID + lane] * a + b : 0.f;
        p0 += fmaxf(v, 0.f);
    }
    float pool = p0 + p1;
    float o0 = pool * w0, o1 = pool * w1;
#pragma unroll
    for (int o = 16; o; o >>= 1) {
        o0 += __shfl_down_sync(0xffffffff, o0, o);
        o1 += __shfl_down_sync(0xffffffff, o1, o);
    }
    if (lane == 0) {
        out[gid * 2 + 0] = o0 + fcb[0];
        out[gid * 2 + 1] = o1 + fcb[1];
    }
}

extern "C" void kernel_launch(void* const* d_in, const int* in_sizes, int n_in,
                              void* d_out, int out_size) {
    const float* x     = (const float*)d_in[0];
    const int*   ei    = (const int*)d_in[1];
    const int*   batch = (const int*)d_in[2];
    const float* W1  = (const float*)d_in[3];
    const float* b1  = (const float*)d_in[4];
    const float* g1  = (const float*)d_in[5];
    const float* be1 = (const float*)d_in[6];
    const float* W2  = (const float*)d_in[7];
    const float* b2  = (const float*)d_in[8];
    const float* g2  = (const float*)d_in[9];
    const float* be2 = (const float*)d_in[10];
    const float* W3  = (const float*)d_in[11];
    const float* b3  = (const float*)d_in[12];
    const float* g3  = (const float*)d_in[13];
    const float* be3 = (const float*)d_in[14];
    const float* fcW = (const float*)d_in[15];
    const float* fcb = (const float*)d_in[16];
    float* out = (float*)d_out;

    // launch order: 0 fillprep, 1 gin1, 2 bnorm1, 3 gin2, 4 bnorm2,
    // 5 gin3 (<- ncu -s 5 -c 1), 6 poolfc
    k_fillprep<<<NB_FILL, 256>>>(ei, x);

    k_gin<IN_DIM, 16, 0, -1><<<NBLK2, 256>>>(W1, b1);
    k_bnorm<0><<<NBLK_N, 256>>>(g1, be1);

    k_gin<HID, 32, 1, 0><<<NBLK2, 256>>>(W2, b2);
    k_bnorm<1><<<NBLK_N, 256>>>(g2, be2);

    k_gin<HID, 32, 2, 1><<<NBLK2, 256>>>(W3, b3);
    k_poolfc<<<(N_GRAPHS + 19) / 20, 640>>>(g3, be3, batch, fcW, fcb, out);
}